// round 6
// baseline (speedup 1.0000x reference)
#include <cuda_runtime.h>
#include <cuda_bf16.h>
#include <cstdint>

// ---------------------------------------------------------------------------
// Problem: B=16, S=512, F=512, H=8, D=512.
// All GEMM operands pre-split into bf16 hi/lo planes (x = hi + lo).
// ---------------------------------------------------------------------------
__device__ float g_V[16 * 512 * 4096];      // V projection fp32 (pre-transpose)
__device__ float g_P[128 * 512 * 512];      // scores fp32 (softmax input)

__device__ __nv_bfloat16 g_xh[8192 * 512],       g_xl[8192 * 512];
__device__ __nv_bfloat16 g_WTh[3 * 4096 * 512],  g_WTl[3 * 4096 * 512];
__device__ __nv_bfloat16 g_Qh[8192 * 4096],      g_Ql[8192 * 4096];
__device__ __nv_bfloat16 g_Kh[8192 * 4096],      g_Kl[8192 * 4096];
__device__ __nv_bfloat16 g_VTh[128 * 512 * 512], g_VTl[128 * 512 * 512];
__device__ __nv_bfloat16 g_Ph[128 * 512 * 512],  g_Pl[128 * 512 * 512];

// ===========================================================================
// Helpers
// ===========================================================================
__device__ __forceinline__ uint32_t smem_u32(const void* p) {
    uint32_t a;
    asm("{ .reg .u64 t; cvta.to.shared.u64 t, %1; cvt.u32.u64 %0, t; }"
        : "=r"(a) : "l"(p));
    return a;
}

__device__ __forceinline__ void cp16(uint32_t dst, const void* src) {
    asm volatile("cp.async.cg.shared.global [%0], [%1], 16;"
                 :: "r"(dst), "l"(src) : "memory");
}
#define CP_COMMIT() asm volatile("cp.async.commit_group;" ::: "memory")
#define CP_WAIT2()  asm volatile("cp.async.wait_group 2;" ::: "memory")

// pack two fp32 into bf16x2 hi-plane word + lo-plane word (rn rounding)
__device__ __forceinline__ void pack2(float x0, float x1, uint32_t& h, uint32_t& l) {
    asm("cvt.rn.bf16x2.f32 %0, %1, %2;" : "=r"(h) : "f"(x1), "f"(x0));
    float f0 = __uint_as_float(h << 16);
    float f1 = __uint_as_float(h & 0xFFFF0000u);
    float l0 = x0 - f0, l1 = x1 - f1;
    asm("cvt.rn.bf16x2.f32 %0, %1, %2;" : "=r"(l) : "f"(l1), "f"(l0));
}

// D += A * B : m16n8k16 bf16, row.col, fp32 accumulate
__device__ __forceinline__ void mma16(float* c, const uint32_t* a, const uint32_t* b) {
    asm volatile(
        "mma.sync.aligned.m16n8k16.row.col.f32.bf16.bf16.f32 "
        "{%0,%1,%2,%3}, {%4,%5,%6,%7}, {%8,%9}, {%0,%1,%2,%3};"
        : "+f"(c[0]), "+f"(c[1]), "+f"(c[2]), "+f"(c[3])
        : "r"(a[0]), "r"(a[1]), "r"(a[2]), "r"(a[3]), "r"(b[0]), "r"(b[1]));
}

__device__ __forceinline__ void ldsm4(uint32_t* r, uint32_t addr) {
    asm volatile("ldmatrix.sync.aligned.m8n8.x4.shared.b16 {%0,%1,%2,%3}, [%4];"
                 : "=r"(r[0]), "=r"(r[1]), "=r"(r[2]), "=r"(r[3]) : "r"(addr));
}

// ===========================================================================
// NT GEMM on bf16 hi/lo planes (3-term emulation of fp32).
//   C[128x256] = A[M,512] @ B[N,512]^T   (planes row-major, K contiguous)
// 256 threads = 8 warps (2M x 4N), warp tile 64x64, m16n8k16 frags.
// SMEM stage (KB=32): each tile row = 128B: chunks 0-3 = hi k0..31,
// chunks 4-7 = lo k0..31, chunk swizzle c ^= (row&7).
//   A rows 0..127 @ [0,16384) ; B rows 0..255 @ [16384,49152)
// 4-stage cp.async ring; fragment loads via ldmatrix.x4 (conflict-free).
// ===========================================================================
#define KB        32
#define NKB       16
#define NSTG      4
#define STAGE     49152
#define GEMM_SMEM (NSTG * STAGE)   // 196608

// EPI: 0 -> write fp32 C;  1 -> write bf16 hi/lo planes Ch/Cl
template <int EPI>
__device__ __forceinline__ void gemm_nt_bf16(
    const __nv_bfloat16* __restrict__ Ah, const __nv_bfloat16* __restrict__ Al, int lda,
    const __nv_bfloat16* __restrict__ Bh, const __nv_bfloat16* __restrict__ Bl, int ldb,
    float* __restrict__ C, __nv_bfloat16* __restrict__ Ch,
    __nv_bfloat16* __restrict__ Cl, int ldc)
{
    extern __shared__ __align__(128) char smc[];
    const uint32_t sa = smem_u32(smc);

    const int tid = threadIdx.x;
    const int wid = tid >> 5;
    const int lid = tid & 31;
    const int wr  = wid >> 2;        // 0..1 (M)
    const int wc  = wid & 3;         // 0..3 (N)
    const int g   = lid >> 2;        // 0..7
    const int tg  = lid & 3;         // 0..3

    const __nv_bfloat16* Abh = Ah + (size_t)(blockIdx.y * 128) * lda;
    const __nv_bfloat16* Abl = Al + (size_t)(blockIdx.y * 128) * lda;
    const __nv_bfloat16* Bbh = Bh + (size_t)(blockIdx.x * 256) * ldb;
    const __nv_bfloat16* Bbl = Bl + (size_t)(blockIdx.x * 256) * ldb;

    // cp.async task decomposition: t -> (row, chunk c). dest swizzled.
    auto load_stage = [&](int buf, int kb) {
        const uint32_t dbase = sa + buf * STAGE;
        const int kc = kb * KB;
#pragma unroll
        for (int i = 0; i < 4; ++i) {               // A: 1024 chunks
            const int t = tid + (i << 8);
            const int row = t >> 3, c = t & 7;
            const __nv_bfloat16* src =
                ((c & 4) ? Abl : Abh) + (size_t)row * lda + kc + (c & 3) * 8;
            cp16(dbase + row * 128 + ((c ^ (row & 7)) << 4), src);
        }
#pragma unroll
        for (int i = 0; i < 8; ++i) {               // B: 2048 chunks
            const int t = tid + (i << 8);
            const int row = t >> 3, c = t & 7;
            const __nv_bfloat16* src =
                ((c & 4) ? Bbl : Bbh) + (size_t)row * ldb + kc + (c & 3) * 8;
            cp16(dbase + 16384 + row * 128 + ((c ^ (row & 7)) << 4), src);
        }
    };

    float acc[4][8][4];
#pragma unroll
    for (int mt = 0; mt < 4; ++mt)
#pragma unroll
        for (int nt = 0; nt < 8; ++nt)
#pragma unroll
            for (int i = 0; i < 4; ++i) acc[mt][nt][i] = 0.0f;

    // ldmatrix per-thread row bases: row = tilebase + (lid&15); note
    // (row&7) == (lid&7) for all our tiles, folded as XOR of (lid&7)<<4.
    const uint32_t sx  = (uint32_t)(lid & 7) << 4;
    const uint32_t hb  = (uint32_t)(lid >> 4) << 4;   // 16B half select
    uint32_t ra[4], rb[4];
#pragma unroll
    for (int mt = 0; mt < 4; ++mt)
        ra[mt] = (uint32_t)(wr * 64 + mt * 16 + (lid & 15)) * 128;
#pragma unroll
    for (int n2 = 0; n2 < 4; ++n2)
        rb[n2] = 16384u + (uint32_t)(wc * 64 + n2 * 16 + (lid & 15)) * 128;

    load_stage(0, 0); CP_COMMIT();
    load_stage(1, 1); CP_COMMIT();
    load_stage(2, 2); CP_COMMIT();

#pragma unroll 1
    for (int kb = 0; kb < NKB; ++kb) {
        CP_WAIT2();
        __syncthreads();
        const uint32_t sbase = sa + (kb & 3) * STAGE;

#pragma unroll
        for (int ks = 0; ks < 2; ++ks) {
            const uint32_t cvh = (uint32_t)(ks << 5) + hb;        // hi chunk<<4
            const uint32_t cvl = cvh + 64;                        // lo chunk<<4

            // ---- B fragments via ldmatrix.x4 (2 nt tiles per op) ----
            uint32_t bhv[8][2], blv[8][2];
#pragma unroll
            for (int n2 = 0; n2 < 4; ++n2) {
                const uint32_t base = sbase + rb[n2];
                uint32_t r[4];
                ldsm4(r, base + (cvh ^ sx));
                bhv[n2 * 2][0] = r[0]; bhv[n2 * 2][1] = r[2];
                bhv[n2 * 2 + 1][0] = r[1]; bhv[n2 * 2 + 1][1] = r[3];
                ldsm4(r, base + (cvl ^ sx));
                blv[n2 * 2][0] = r[0]; blv[n2 * 2][1] = r[2];
                blv[n2 * 2 + 1][0] = r[1]; blv[n2 * 2 + 1][1] = r[3];
            }

#pragma unroll
            for (int mt = 0; mt < 4; ++mt) {
                const uint32_t base = sbase + ra[mt];
                uint32_t ah[4], al[4];
                ldsm4(ah, base + (cvh ^ sx));
                ldsm4(al, base + (cvl ^ sx));
#pragma unroll
                for (int nt = 0; nt < 8; ++nt) mma16(acc[mt][nt], ah, bhv[nt]);
#pragma unroll
                for (int nt = 0; nt < 8; ++nt) mma16(acc[mt][nt], ah, blv[nt]);
#pragma unroll
                for (int nt = 0; nt < 8; ++nt) mma16(acc[mt][nt], al, bhv[nt]);
            }
        }

        if (kb + 3 < NKB) load_stage((kb + 3) & 3, kb + 3);
        CP_COMMIT();
    }

    // ---- epilogue ----
    const int rbase = blockIdx.y * 128 + wr * 64 + g;
    const int cbase = blockIdx.x * 256 + wc * 64 + tg * 2;
#pragma unroll
    for (int mt = 0; mt < 4; ++mt) {
#pragma unroll
        for (int nt = 0; nt < 8; ++nt) {
            const int r = rbase + mt * 16;
            const int c = cbase + nt * 8;
            if (EPI == 0) {
                *reinterpret_cast<float2*>(&C[(size_t)r * ldc + c]) =
                    make_float2(acc[mt][nt][0], acc[mt][nt][1]);
                *reinterpret_cast<float2*>(&C[(size_t)(r + 8) * ldc + c]) =
                    make_float2(acc[mt][nt][2], acc[mt][nt][3]);
            } else {
                uint32_t h, l;
                pack2(acc[mt][nt][0], acc[mt][nt][1], h, l);
                *reinterpret_cast<uint32_t*>(Ch + (size_t)r * ldc + c) = h;
                *reinterpret_cast<uint32_t*>(Cl + (size_t)r * ldc + c) = l;
                pack2(acc[mt][nt][2], acc[mt][nt][3], h, l);
                *reinterpret_cast<uint32_t*>(Ch + (size_t)(r + 8) * ldc + c) = h;
                *reinterpret_cast<uint32_t*>(Cl + (size_t)(r + 8) * ldc + c) = l;
            }
        }
    }
}

// ===========================================================================
// GEMM wrappers
// ===========================================================================
__global__ void __launch_bounds__(256, 1)
proj_mm()
{
    const int z = blockIdx.z;                 // 0:Q 1:K 2:V
    const __nv_bfloat16* Bh = g_WTh + (size_t)z * 4096 * 512;
    const __nv_bfloat16* Bl = g_WTl + (size_t)z * 4096 * 512;
    if (z == 0) {
        gemm_nt_bf16<1>(g_xh, g_xl, 512, Bh, Bl, 512, nullptr, g_Qh, g_Ql, 4096);
    } else if (z == 1) {
        gemm_nt_bf16<1>(g_xh, g_xl, 512, Bh, Bl, 512, nullptr, g_Kh, g_Kl, 4096);
    } else {
        gemm_nt_bf16<0>(g_xh, g_xl, 512, Bh, Bl, 512, g_V, nullptr, nullptr, 4096);
    }
}

__global__ void __launch_bounds__(256, 1)
qk_mm()
{
    const int z = blockIdx.z;                 // h*16 + b
    const int h = z >> 4, b = z & 15;
    const size_t off = (size_t)b * 512 * 4096 + h * 512;
    gemm_nt_bf16<0>(g_Qh + off, g_Ql + off, 4096,
                    g_Kh + off, g_Kl + off, 4096,
                    g_P + (size_t)z * 512 * 512, nullptr, nullptr, 512);
}

__global__ void __launch_bounds__(256, 1)
pv_mm(float* __restrict__ out)
{
    const int z = blockIdx.z;
    const int h = z >> 4, b = z & 15;
    const size_t zo = (size_t)z * 512 * 512;
    gemm_nt_bf16<0>(g_Ph + zo, g_Pl + zo, 512,
                    g_VTh + zo, g_VTl + zo, 512,
                    out + (size_t)b * 512 * 4096 + h * 512, nullptr, nullptr, 4096);
}

// ===========================================================================
// Splits / transposes
// ===========================================================================
__global__ void split_x(const float* __restrict__ x)
{
    const size_t i = ((size_t)blockIdx.x * 256 + threadIdx.x) * 4;
    const float4 v = *reinterpret_cast<const float4*>(x + i);
    uint32_t h0, l0, h1, l1;
    pack2(v.x, v.y, h0, l0);
    pack2(v.z, v.w, h1, l1);
    *reinterpret_cast<uint2*>(g_xh + i) = make_uint2(h0, h1);
    *reinterpret_cast<uint2*>(g_xl + i) = make_uint2(l0, l1);
}

__global__ void wt_kernel(const float* __restrict__ wq,
                          const float* __restrict__ wk,
                          const float* __restrict__ wv)
{
    __shared__ float t[32][33];
    const int z = blockIdx.z;
    const float* W = (z == 0) ? wq : (z == 1) ? wk : wv;   // [512, 4096]
    __nv_bfloat16* WTh = g_WTh + (size_t)z * 4096 * 512;
    __nv_bfloat16* WTl = g_WTl + (size_t)z * 4096 * 512;
    const int n0 = blockIdx.x * 32, k0 = blockIdx.y * 32;
    const int tx = threadIdx.x, ty = threadIdx.y;
#pragma unroll
    for (int i = 0; i < 4; ++i)
        t[ty + i * 8][tx] = W[(size_t)(k0 + ty + i * 8) * 4096 + n0 + tx];
    __syncthreads();
#pragma unroll
    for (int i = 0; i < 4; ++i) {
        const float v = t[tx][ty + i * 8];
        const __nv_bfloat16 hbf = __float2bfloat16_rn(v);
        const float lo = v - __bfloat162float(hbf);
        const size_t idx = (size_t)(n0 + ty + i * 8) * 512 + k0 + tx;
        WTh[idx] = hbf;
        WTl[idx] = __float2bfloat16_rn(lo);
    }
}

__global__ void vt_kernel()
{
    __shared__ float t[32][33];
    const int z = blockIdx.z;                 // h*16 + b
    const int h = z >> 4, b = z & 15;
    const int j0 = blockIdx.x * 32, d0 = blockIdx.y * 32;
    const int tx = threadIdx.x, ty = threadIdx.y;
#pragma unroll
    for (int i = 0; i < 4; ++i)
        t[ty + i * 8][tx] = g_V[(size_t)(b * 512 + j0 + ty + i * 8) * 4096 + h * 512 + d0 + tx];
    __syncthreads();
    __nv_bfloat16* VTh = g_VTh + (size_t)z * 512 * 512;
    __nv_bfloat16* VTl = g_VTl + (size_t)z * 512 * 512;
#pragma unroll
    for (int i = 0; i < 4; ++i) {
        const float v = t[tx][ty + i * 8];
        const __nv_bfloat16 hbf = __float2bfloat16_rn(v);
        const float lo = v - __bfloat162float(hbf);
        const size_t idx = (size_t)(d0 + ty + i * 8) * 512 + j0 + tx;
        VTh[idx] = hbf;
        VTl[idx] = __float2bfloat16_rn(lo);
    }
}

// ===========================================================================
// Softmax over rows of g_P (512 wide), writes bf16 hi/lo planes.
// ===========================================================================
__global__ void softmax_kernel()
{
    const size_t row = blockIdx.x;
    const float* p = g_P + row * 512;
    const int t = threadIdx.x;  // 0..255

    float2 v = reinterpret_cast<const float2*>(p)[t];
    __shared__ float red[8];

    float m = fmaxf(v.x, v.y);
#pragma unroll
    for (int o = 16; o > 0; o >>= 1) m = fmaxf(m, __shfl_xor_sync(0xFFFFFFFFu, m, o));
    if ((t & 31) == 0) red[t >> 5] = m;
    __syncthreads();
    m = red[0];
#pragma unroll
    for (int i = 1; i < 8; i++) m = fmaxf(m, red[i]);
    __syncthreads();

    const float e0 = __expf(v.x - m);
    const float e1 = __expf(v.y - m);

    float s = e0 + e1;
#pragma unroll
    for (int o = 16; o > 0; o >>= 1) s += __shfl_xor_sync(0xFFFFFFFFu, s, o);
    if ((t & 31) == 0) red[t >> 5] = s;
    __syncthreads();
    s = red[0];
#pragma unroll
    for (int i = 1; i < 8; i++) s += red[i];

    const float inv = 1.0f / s;
    uint32_t h, l;
    pack2(e0 * inv, e1 * inv, h, l);
    reinterpret_cast<uint32_t*>(g_Ph + row * 512)[t] = h;
    reinterpret_cast<uint32_t*>(g_Pl + row * 512)[t] = l;
}

// ===========================================================================
// Launch
// ===========================================================================
extern "C" void kernel_launch(void* const* d_in, const int* in_sizes, int n_in,
                              void* d_out, int out_size)
{
    const float* x  = (const float*)d_in[0];
    const float* wq = (const float*)d_in[1];
    const float* wk = (const float*)d_in[2];
    const float* wv = (const float*)d_in[3];
    float* out = (float*)d_out;

    cudaFuncSetAttribute(proj_mm, cudaFuncAttributeMaxDynamicSharedMemorySize, GEMM_SMEM);
    cudaFuncSetAttribute(qk_mm,   cudaFuncAttributeMaxDynamicSharedMemorySize, GEMM_SMEM);
    cudaFuncSetAttribute(pv_mm,   cudaFuncAttributeMaxDynamicSharedMemorySize, GEMM_SMEM);

    split_x<<<4096, 256>>>(x);                              // x -> hi/lo planes
    wt_kernel<<<dim3(128, 16, 3), dim3(32, 8)>>>(wq, wk, wv);
    proj_mm<<<dim3(16, 64, 3), 256, GEMM_SMEM>>>();         // Q,K planes; V fp32
    vt_kernel<<<dim3(16, 16, 128), dim3(32, 8)>>>();        // V -> VT planes
    qk_mm<<<dim3(2, 4, 128), 256, GEMM_SMEM>>>();           // scores fp32
    softmax_kernel<<<65536, 256>>>();                       // -> P planes
    pv_mm<<<dim3(2, 4, 128), 256, GEMM_SMEM>>>(out);        // out fp32
}